// round 4
// baseline (speedup 1.0000x reference)
#include <cuda_runtime.h>
#include <cuda_bf16.h>
#include <cstdint>

// Shapes (fixed for this problem)
#define N_TOTAL (64 * 4096)      // 262144 nodes
#define NHID    128
#define NN      4096             // nodes per graph == w3 dim
#define MB      64               // batch (graphs)

// ---------------- scratch (device globals; no allocation allowed) ----------
__device__ __align__(16) float2 g_fd [N_TOTAL];   // {agg1, deg} interleaved
__device__ float g_s   [N_TOTAL];
__device__ float g_t   [N_TOTAL];
__device__ float g_agg2[N_TOTAL];
#define GEMM_KSPLIT 8
__device__ float g_part[GEMM_KSPLIT * N_TOTAL];       // split-K partials (8MB)
__device__ __align__(16) unsigned short g_Ah[N_TOTAL];  // A bf16 hi
__device__ __align__(16) unsigned short g_Al[N_TOTAL];  // A bf16 lo
__device__ __align__(16) unsigned short g_Bh[NN * NN];  // w3 bf16 hi (32MB)
__device__ __align__(16) unsigned short g_Bl[NN * NN];  // w3 bf16 lo (32MB)

#define C_2LOG2E 2.88539008177792681f   // 2*log2(e)

__device__ __forceinline__ float ex2f(float x) {
    float e; asm("ex2.approx.f32 %0, %1;" : "=f"(e) : "f"(x)); return e;
}
__device__ __forceinline__ float rcpf(float x) {
    float r; asm("rcp.approx.f32 %0, %1;" : "=f"(r) : "f"(x)); return r;
}
// single tanh from prescaled xp = 2*log2e*x
__device__ __forceinline__ float tanh_exp2(float xp) {
    return fmaf(-2.0f, rcpf(ex2f(xp) + 1.0f), 1.0f);
}

// split two floats into packed bf16 hi pair + bf16 lo pair
__device__ __forceinline__ void split2(float a, float b,
                                       uint32_t& hi, uint32_t& lo) {
    __nv_bfloat16 ha = __float2bfloat16_rn(a);
    __nv_bfloat16 hb = __float2bfloat16_rn(b);
    float la = a - __bfloat162float(ha);
    float lb = b - __bfloat162float(hb);
    __nv_bfloat16 hla = __float2bfloat16_rn(la);
    __nv_bfloat16 hlb = __float2bfloat16_rn(lb);
    hi = (uint32_t)*reinterpret_cast<unsigned short*>(&ha) |
         ((uint32_t)*reinterpret_cast<unsigned short*>(&hb) << 16);
    lo = (uint32_t)*reinterpret_cast<unsigned short*>(&hla) |
         ((uint32_t)*reinterpret_cast<unsigned short*>(&hlb) << 16);
}

// ---------------- kernel 0: zero scratch (vectorized) -----------------------
__global__ void k_zero(int n4) {   // n4 = N_TOTAL/4
    int i = blockIdx.x * blockDim.x + threadIdx.x;
    if (i < n4) {
        float4 z = make_float4(0.f, 0.f, 0.f, 0.f);
        reinterpret_cast<float4*>(g_fd)[2 * i]     = z;
        reinterpret_cast<float4*>(g_fd)[2 * i + 1] = z;
        reinterpret_cast<float4*>(g_agg2)[i]       = z;
    }
}

// ---------------- side-branch kernel: w3 -> bf16 hi/lo (overlapped) ---------
__global__ void k_conv(const float* __restrict__ w3, int n4) {  // n4 = NN*NN/4
    int i = blockIdx.x * blockDim.x + threadIdx.x;
    if (i < n4) {
        float4 v = reinterpret_cast<const float4*>(w3)[i];
        uint32_t h0, l0, h1, l1;
        split2(v.x, v.y, h0, l0);
        split2(v.z, v.w, h1, l1);
        reinterpret_cast<uint2*>(g_Bh)[i] = make_uint2(h0, h1);
        reinterpret_cast<uint2*>(g_Bl)[i] = make_uint2(l0, l1);
    }
}

// ---------------- kernel 1: edge scatter pass 1 ({agg1,deg} v2 red) ---------
__global__ void k_edge1(const float* __restrict__ feat,
                        const int* __restrict__ src,
                        const int* __restrict__ dst, int E) {
    int e = blockIdx.x * blockDim.x + threadIdx.x;
    if (e < E) {
        int s = src[e];
        int d = dst[e];
        float v = __ldg(&feat[s]);
        asm volatile("red.global.add.v2.f32 [%0], {%1, %2};"
                     :: "l"(g_fd + d), "f"(v), "f"(1.0f) : "memory");
    }
}

// ---------------- kernel 2: per-node 128-wide tanh layer --------------------
// 4-way batched reciprocal: 1 rcp serves 4 tanh (xp clamped to <=17 so the
// 4-product of (exp2(xp)+1) stays finite in fp32; abs err <= 1.5e-5).
__global__ __launch_bounds__(256) void k_node1(
        const float* __restrict__ feat,
        const float* __restrict__ ws1, const float* __restrict__ wn1,
        const float* __restrict__ b1,
        const float* __restrict__ ws2, const float* __restrict__ wn2,
        int n_total) {
    __shared__ float4 wA[NHID];   // {C*ws1, C*wn1, C*b1, ws2}  (prescaled)
    __shared__ float  wB[NHID];   // wn2
    int t = threadIdx.x;
    if (t < NHID) {
        wA[t] = make_float4(C_2LOG2E * ws1[t], C_2LOG2E * wn1[t],
                            C_2LOG2E * b1[t], ws2[t]);
        wB[t] = wn2[t];
    }
    __syncthreads();

    int n = blockIdx.x * blockDim.x + t;
    if (n >= n_total) return;

    float f   = feat[n];
    float2 fd = g_fd[n];
    float g   = __fdividef(fd.x, fmaxf(fd.y, 1.0f));

    float sacc = 0.0f, tacc = 0.0f;
#pragma unroll 4
    for (int j = 0; j < NHID; j += 4) {
        float a[4];
#pragma unroll
        for (int u = 0; u < 4; u++) {
            float4 w = wA[j + u];
            float xp = fminf(fmaf(f, w.x, fmaf(g, w.y, w.z)), 17.0f);
            a[u] = ex2f(xp) + 1.0f;
        }
        float p1 = a[0] * a[1];
        float p2 = a[2] * a[3];
        float r  = rcpf(p1 * p2);
        float q1 = r * p2;   // 1/(a0*a1)
        float q2 = r * p1;   // 1/(a2*a3)
        float inv[4];
        inv[0] = q1 * a[1];
        inv[1] = q1 * a[0];
        inv[2] = q2 * a[3];
        inv[3] = q2 * a[2];
#pragma unroll
        for (int u = 0; u < 4; u++) {
            float rr = fmaf(-2.0f, inv[u], 1.0f);
            sacc = fmaf(rr, wA[j + u].w, sacc);
            tacc = fmaf(rr, wB[j + u], tacc);
        }
    }
    g_s[n] = sacc;
    g_t[n] = tacc;
}

// ---------------- kernel 3: edge scatter pass 2 (agg2 of t) -----------------
__global__ void k_edge2(const int* __restrict__ src,
                        const int* __restrict__ dst, int E) {
    int e = blockIdx.x * blockDim.x + threadIdx.x;
    if (e < E) {
        atomicAdd(&g_agg2[dst[e]], __ldg(&g_t[src[e]]));
    }
}

// ---------------- kernel 4: out1; A = split(tanh(out1)) ---------------------
__global__ void k_node2(const float* __restrict__ b2,
                        float* __restrict__ out, int n_total) {
    int n = blockIdx.x * blockDim.x + threadIdx.x;
    if (n < n_total) {
        float o = g_s[n] + __fdividef(g_agg2[n], fmaxf(g_fd[n].y, 1.0f)) + b2[0];
        out[n] = o;                          // output1
        float h = tanh_exp2(C_2LOG2E * o);
        __nv_bfloat16 hh = __float2bfloat16_rn(h);
        float lo = h - __bfloat162float(hh);
        __nv_bfloat16 hl = __float2bfloat16_rn(lo);
        g_Ah[n] = *reinterpret_cast<unsigned short*>(&hh);
        g_Al[n] = *reinterpret_cast<unsigned short*>(&hl);
    }
}

// ---------------- kernel 5: GEMM partials (preconverted bf16 operands) ------
// 3 passes: Ah*Bh + Ah*Bl + Al*Bh via mma.m16n8k16.bf16 (rel err ~2^-17).
// Grid: 32 n-tiles (BN=128) x KSPLIT=8 (K range 512, 32 chunks of 16).
#define GEMM_BN 128
#define GEMM_KRANGE (NN / GEMM_KSPLIT)   // 512
#define GEMM_NCHUNK (GEMM_KRANGE / 16)   // 32

__device__ __forceinline__ void mma_bf16(float c[4], const uint32_t a[4],
                                         const uint32_t b[2]) {
    asm volatile(
        "mma.sync.aligned.m16n8k16.row.col.f32.bf16.bf16.f32 "
        "{%0,%1,%2,%3}, {%4,%5,%6,%7}, {%8,%9}, {%0,%1,%2,%3};\n"
        : "+f"(c[0]), "+f"(c[1]), "+f"(c[2]), "+f"(c[3])
        : "r"(a[0]), "r"(a[1]), "r"(a[2]), "r"(a[3]), "r"(b[0]), "r"(b[1]));
}
__device__ __forceinline__ void ldsm_x4(uint32_t r[4], uint32_t addr) {
    asm volatile("ldmatrix.sync.aligned.m8n8.x4.shared.b16 {%0,%1,%2,%3}, [%4];"
                 : "=r"(r[0]), "=r"(r[1]), "=r"(r[2]), "=r"(r[3]) : "r"(addr));
}
__device__ __forceinline__ void ldsm_x2t(uint32_t r[2], uint32_t addr) {
    asm volatile("ldmatrix.sync.aligned.m8n8.x2.trans.shared.b16 {%0,%1}, [%2];"
                 : "=r"(r[0]), "=r"(r[1]) : "r"(addr));
}

__global__ __launch_bounds__(256) void k_gemm() {
    __shared__ __align__(16) unsigned short sAh[2][MB][16], sAl[2][MB][16];
    __shared__ __align__(16) unsigned short sBh[2][16][GEMM_BN], sBl[2][16][GEMM_BN];

    int tid  = threadIdx.x;
    int warp = tid >> 5;
    int lane = tid & 31;
    int g    = lane >> 2;
    int tg   = lane & 3;
    int n0   = blockIdx.x * GEMM_BN;
    int kb   = blockIdx.y * GEMM_KRANGE;

    int rA = tid >> 2;              // 0..63
    int cA = (tid & 3) * 4;         // ushort col
    int rB = tid >> 4;              // 0..15
    int cB = (tid & 15) * 8;        // ushort col

    float acc[4][2][4];
#pragma unroll
    for (int mi = 0; mi < 4; mi++)
#pragma unroll
        for (int ni = 0; ni < 2; ni++)
#pragma unroll
            for (int r = 0; r < 4; r++) acc[mi][ni][r] = 0.0f;

    // prefetch chunk 0
    uint2 rah, ral; uint4 rbh, rbl;
    {
        int k0 = kb;
        rah = *reinterpret_cast<const uint2*>(&g_Ah[rA * NN + k0 + cA]);
        ral = *reinterpret_cast<const uint2*>(&g_Al[rA * NN + k0 + cA]);
        rbh = *reinterpret_cast<const uint4*>(&g_Bh[(size_t)(k0 + rB) * NN + n0 + cB]);
        rbl = *reinterpret_cast<const uint4*>(&g_Bl[(size_t)(k0 + rB) * NN + n0 + cB]);
    }

    uint32_t aAh = (uint32_t)__cvta_generic_to_shared(
        &sAh[0][(lane & 15)][(lane >> 4) * 8]);
    uint32_t aAl = (uint32_t)__cvta_generic_to_shared(
        &sAl[0][(lane & 15)][(lane >> 4) * 8]);
    uint32_t aBh = (uint32_t)__cvta_generic_to_shared(
        &sBh[0][(lane & 15)][warp * 16]);
    uint32_t aBl = (uint32_t)__cvta_generic_to_shared(
        &sBl[0][(lane & 15)][warp * 16]);
    const uint32_t strideAbuf = MB * 16 * 2;
    const uint32_t strideBbuf = 16 * GEMM_BN * 2;

    int p = 0;
#pragma unroll 1
    for (int ck = 0; ck < GEMM_NCHUNK; ck++) {
        *reinterpret_cast<uint2*>(&sAh[p][rA][cA]) = rah;
        *reinterpret_cast<uint2*>(&sAl[p][rA][cA]) = ral;
        *reinterpret_cast<uint4*>(&sBh[p][rB][cB]) = rbh;
        *reinterpret_cast<uint4*>(&sBl[p][rB][cB]) = rbl;

        if (ck + 1 < GEMM_NCHUNK) {
            int k0 = kb + (ck + 1) * 16;
            rah = *reinterpret_cast<const uint2*>(&g_Ah[rA * NN + k0 + cA]);
            ral = *reinterpret_cast<const uint2*>(&g_Al[rA * NN + k0 + cA]);
            rbh = *reinterpret_cast<const uint4*>(&g_Bh[(size_t)(k0 + rB) * NN + n0 + cB]);
            rbl = *reinterpret_cast<const uint4*>(&g_Bl[(size_t)(k0 + rB) * NN + n0 + cB]);
        }
        __syncthreads();

        uint32_t aH[4][4], aL[4][4];
#pragma unroll
        for (int mi = 0; mi < 4; mi++) {
            ldsm_x4(aH[mi], aAh + p * strideAbuf + mi * 16 * 16 * 2);
            ldsm_x4(aL[mi], aAl + p * strideAbuf + mi * 16 * 16 * 2);
        }
        uint32_t bH[2][2], bL[2][2];
#pragma unroll
        for (int ni = 0; ni < 2; ni++) {
            ldsm_x2t(bH[ni], aBh + p * strideBbuf + ni * 8 * 2);
            ldsm_x2t(bL[ni], aBl + p * strideBbuf + ni * 8 * 2);
        }
#pragma unroll
        for (int mi = 0; mi < 4; mi++)
#pragma unroll
            for (int ni = 0; ni < 2; ni++) {
                mma_bf16(acc[mi][ni], aH[mi], bH[ni]);
                mma_bf16(acc[mi][ni], aH[mi], bL[ni]);
                mma_bf16(acc[mi][ni], aL[mi], bH[ni]);
            }
        p ^= 1;
        __syncthreads();
    }

    float* part = g_part + (size_t)blockIdx.y * N_TOTAL;
#pragma unroll
    for (int mi = 0; mi < 4; mi++) {
        int row = mi * 16 + g;
#pragma unroll
        for (int ni = 0; ni < 2; ni++) {
            int col = n0 + warp * 16 + ni * 8 + 2 * tg;
            *reinterpret_cast<float2*>(&part[(size_t)row * NN + col]) =
                make_float2(acc[mi][ni][0], acc[mi][ni][1]);
            *reinterpret_cast<float2*>(&part[(size_t)(row + 8) * NN + col]) =
                make_float2(acc[mi][ni][2], acc[mi][ni][3]);
        }
    }
}

// ---------------- kernel 6: reduce split-K partials + b3 --------------------
__global__ void k_red(const float* __restrict__ b3,
                      float* __restrict__ out2, int n4) {  // n4 = N_TOTAL/4
    int i = blockIdx.x * blockDim.x + threadIdx.x;
    if (i < n4) {
        float4 a = reinterpret_cast<const float4*>(b3)[i & (NN / 4 - 1)];
#pragma unroll
        for (int j = 0; j < GEMM_KSPLIT; j++) {
            float4 pv = reinterpret_cast<const float4*>(g_part)[(size_t)j * (N_TOTAL / 4) + i];
            a.x += pv.x; a.y += pv.y; a.z += pv.z; a.w += pv.w;
        }
        reinterpret_cast<float4*>(out2)[i] = a;
    }
}

// ---------------- launch ----------------------------------------------------
extern "C" void kernel_launch(void* const* d_in, const int* in_sizes, int n_in,
                              void* d_out, int out_size) {
    const float* feat = (const float*)d_in[0];
    const int*   src  = (const int*)d_in[1];
    const int*   dst  = (const int*)d_in[2];
    const float* ws1  = (const float*)d_in[3];
    const float* wn1  = (const float*)d_in[4];
    const float* b1   = (const float*)d_in[5];
    const float* ws2  = (const float*)d_in[6];
    const float* wn2  = (const float*)d_in[7];
    const float* b2   = (const float*)d_in[8];
    const float* w3   = (const float*)d_in[9];
    const float* b3   = (const float*)d_in[10];
    float* out = (float*)d_out;

    int N = in_sizes[0];   // 262144
    int E = in_sizes[1];   // 2097152

    // side stream for w3 preconversion (fork/join so graph capture records
    // a parallel branch; no sync calls, no allocation)
    cudaStream_t s2;
    cudaStreamCreateWithFlags(&s2, cudaStreamNonBlocking);
    cudaEvent_t eF, eJ;
    cudaEventCreateWithFlags(&eF, cudaEventDisableTiming);
    cudaEventCreateWithFlags(&eJ, cudaEventDisableTiming);

    cudaEventRecord(eF, 0);
    cudaStreamWaitEvent(s2, eF, 0);
    int w4 = NN * NN / 4;
    k_conv<<<(w4 + 255) / 256, 256, 0, s2>>>(w3, w4);
    cudaEventRecord(eJ, s2);

    k_zero<<<(N / 4 + 255) / 256, 256>>>(N / 4);
    k_edge1<<<(E + 255) / 256, 256>>>(feat, src, dst, E);
    k_node1<<<(N + 255) / 256, 256>>>(feat, ws1, wn1, b1, ws2, wn2, N);
    k_edge2<<<(E + 255) / 256, 256>>>(src, dst, E);
    k_node2<<<(N + 255) / 256, 256>>>(b2, out, N);

    cudaStreamWaitEvent(0, eJ, 0);
    dim3 grid(NN / GEMM_BN, GEMM_KSPLIT);
    k_gemm<<<grid, 256>>>();
    k_red<<<(N / 4 + 255) / 256, 256>>>(b3, out + N, N / 4);
}

// round 5
// speedup vs baseline: 1.1628x; 1.1628x over previous
#include <cuda_runtime.h>
#include <cuda_bf16.h>
#include <cstdint>

// Shapes (fixed for this problem)
#define N_TOTAL (64 * 4096)      // 262144 nodes
#define NHID    128
#define NN      4096             // nodes per graph == w3 dim
#define MB      64               // batch (graphs)

// ---------------- scratch (device globals; no allocation allowed) ----------
__device__ __align__(16) float2 g_fd [N_TOTAL];   // {agg1, deg} interleaved
__device__ float g_s   [N_TOTAL];
__device__ float g_t   [N_TOTAL];
__device__ float g_agg2[N_TOTAL];
#define GEMM_KSPLIT 8
__device__ float g_part[GEMM_KSPLIT * N_TOTAL];        // split-K partials (8MB)
__device__ __align__(16) unsigned short g_Ah[N_TOTAL]; // A bf16 hi
__device__ __align__(16) unsigned short g_Al[N_TOTAL]; // A bf16 lo

#define C_2LOG2E 2.88539008177792681f   // 2*log2(e)

__device__ __forceinline__ float ex2f(float x) {
    float e; asm("ex2.approx.f32 %0, %1;" : "=f"(e) : "f"(x)); return e;
}
__device__ __forceinline__ float rcpf(float x) {
    float r; asm("rcp.approx.f32 %0, %1;" : "=f"(r) : "f"(x)); return r;
}
// tanh from prescaled xp = 2*log2e*x : tanh = 1 - 2/(exp2(xp)+1)
__device__ __forceinline__ float tanh_exp2(float xp) {
    return fmaf(-2.0f, rcpf(ex2f(xp) + 1.0f), 1.0f);
}

// fast hi/lo bf16 split of two floats: hi = truncation (PRMT pack),
// lo = exact residual rounded to bf16 (packed cvt). 6 ops / 2 floats.
__device__ __forceinline__ void split2_fast(float a, float b,
                                            uint32_t& hi, uint32_t& lo) {
    uint32_t ua = __float_as_uint(a), ub = __float_as_uint(b);
    hi = __byte_perm(ua, ub, 0x7632);                   // {a_hi16, b_hi16}
    float ah = __uint_as_float(ua & 0xFFFF0000u);
    float bh = __uint_as_float(ub & 0xFFFF0000u);
    float la = a - ah, lb = b - bh;
    asm("cvt.rn.satfinite.bf16x2.f32 %0, %1, %2;" : "=r"(lo) : "f"(lb), "f"(la));
}

// ---------------- side-branch: L2 prefetch of w3 (footprint-light) ----------
__global__ void k_pref(const float* __restrict__ w3) {
    const char* p = reinterpret_cast<const char*>(w3);
    size_t nlines = (size_t)NN * NN * 4 / 128;           // 512K lines
    for (size_t i = blockIdx.x * blockDim.x + threadIdx.x; i < nlines;
         i += (size_t)gridDim.x * blockDim.x) {
        asm volatile("prefetch.global.L2 [%0];" :: "l"(p + i * 128));
    }
}

// ---------------- kernel 0: zero scratch (vectorized) -----------------------
__global__ void k_zero(int n4) {   // n4 = N_TOTAL/4
    int i = blockIdx.x * blockDim.x + threadIdx.x;
    if (i < n4) {
        float4 z = make_float4(0.f, 0.f, 0.f, 0.f);
        reinterpret_cast<float4*>(g_fd)[2 * i]     = z;
        reinterpret_cast<float4*>(g_fd)[2 * i + 1] = z;
        reinterpret_cast<float4*>(g_agg2)[i]       = z;
    }
}

// ---------------- kernel 1: edge scatter pass 1 ({agg1,deg} v2 red) ---------
__global__ void k_edge1(const float* __restrict__ feat,
                        const int* __restrict__ src,
                        const int* __restrict__ dst, int E) {
    int e = blockIdx.x * blockDim.x + threadIdx.x;
    if (e < E) {
        int s = src[e];
        int d = dst[e];
        float v = __ldg(&feat[s]);
        asm volatile("red.global.add.v2.f32 [%0], {%1, %2};"
                     :: "l"(g_fd + d), "f"(v), "f"(1.0f) : "memory");
    }
}

// ---------------- kernel 2: per-node 128-wide tanh layer (simple, 2 MUFU) ---
__global__ __launch_bounds__(256) void k_node1(
        const float* __restrict__ feat,
        const float* __restrict__ ws1, const float* __restrict__ wn1,
        const float* __restrict__ b1,
        const float* __restrict__ ws2, const float* __restrict__ wn2,
        int n_total) {
    __shared__ float4 wA[NHID];   // {C*ws1, C*wn1, C*b1, ws2}  (prescaled)
    __shared__ float  wB[NHID];   // wn2
    int t = threadIdx.x;
    if (t < NHID) {
        wA[t] = make_float4(C_2LOG2E * ws1[t], C_2LOG2E * wn1[t],
                            C_2LOG2E * b1[t], ws2[t]);
        wB[t] = wn2[t];
    }
    __syncthreads();

    int n = blockIdx.x * blockDim.x + t;
    if (n >= n_total) return;

    float f   = feat[n];
    float2 fd = g_fd[n];
    float g   = __fdividef(fd.x, fmaxf(fd.y, 1.0f));

    float sacc = 0.0f, tacc = 0.0f;
#pragma unroll 8
    for (int j = 0; j < NHID; j++) {
        float4 w = wA[j];
        float xp = fmaf(f, w.x, fmaf(g, w.y, w.z));
        float r = tanh_exp2(xp);
        sacc = fmaf(r, w.w, sacc);
        tacc = fmaf(r, wB[j], tacc);
    }
    g_s[n] = sacc;
    g_t[n] = tacc;
}

// ---------------- kernel 3: edge scatter pass 2 (agg2 of t) -----------------
__global__ void k_edge2(const int* __restrict__ src,
                        const int* __restrict__ dst, int E) {
    int e = blockIdx.x * blockDim.x + threadIdx.x;
    if (e < E) {
        atomicAdd(&g_agg2[dst[e]], __ldg(&g_t[src[e]]));
    }
}

// ---------------- kernel 4: out1; A = split(tanh(out1)) ---------------------
__global__ void k_node2(const float* __restrict__ b2,
                        float* __restrict__ out, int n_total) {
    int n = blockIdx.x * blockDim.x + threadIdx.x;
    if (n < n_total) {
        float o = g_s[n] + __fdividef(g_agg2[n], fmaxf(g_fd[n].y, 1.0f)) + b2[0];
        out[n] = o;                          // output1
        float h = tanh_exp2(C_2LOG2E * o);
        __nv_bfloat16 hh = __float2bfloat16_rn(h);
        float lo = h - __bfloat162float(hh);
        __nv_bfloat16 hl = __float2bfloat16_rn(lo);
        g_Ah[n] = *reinterpret_cast<unsigned short*>(&hh);
        g_Al[n] = *reinterpret_cast<unsigned short*>(&hl);
    }
}

// ---------------- kernel 5: GEMM partials = h2 @ w3 (bf16 3-pass split) -----
// A preconverted (g_Ah/g_Al); B converted inline with split2_fast from
// L2-prefetched w3. Grid: 32 n-tiles (BN=128) x KSPLIT=8; non-atomic stores.
#define GEMM_BN 128
#define GEMM_KRANGE (NN / GEMM_KSPLIT)   // 512
#define GEMM_NCHUNK (GEMM_KRANGE / 16)   // 32

__device__ __forceinline__ void mma_bf16(float c[4], const uint32_t a[4],
                                         const uint32_t b[2]) {
    asm volatile(
        "mma.sync.aligned.m16n8k16.row.col.f32.bf16.bf16.f32 "
        "{%0,%1,%2,%3}, {%4,%5,%6,%7}, {%8,%9}, {%0,%1,%2,%3};\n"
        : "+f"(c[0]), "+f"(c[1]), "+f"(c[2]), "+f"(c[3])
        : "r"(a[0]), "r"(a[1]), "r"(a[2]), "r"(a[3]), "r"(b[0]), "r"(b[1]));
}
__device__ __forceinline__ void ldsm_x4(uint32_t r[4], uint32_t addr) {
    asm volatile("ldmatrix.sync.aligned.m8n8.x4.shared.b16 {%0,%1,%2,%3}, [%4];"
                 : "=r"(r[0]), "=r"(r[1]), "=r"(r[2]), "=r"(r[3]) : "r"(addr));
}
__device__ __forceinline__ void ldsm_x2t(uint32_t r[2], uint32_t addr) {
    asm volatile("ldmatrix.sync.aligned.m8n8.x2.trans.shared.b16 {%0,%1}, [%2];"
                 : "=r"(r[0]), "=r"(r[1]) : "r"(addr));
}

__global__ __launch_bounds__(256) void k_gemm(const float* __restrict__ w3) {
    __shared__ __align__(16) unsigned short sAh[2][MB][16], sAl[2][MB][16];
    __shared__ __align__(16) unsigned short sBh[2][16][GEMM_BN], sBl[2][16][GEMM_BN];

    int tid  = threadIdx.x;
    int warp = tid >> 5;
    int lane = tid & 31;
    int g    = lane >> 2;
    int tg   = lane & 3;
    int n0   = blockIdx.x * GEMM_BN;
    int kb   = blockIdx.y * GEMM_KRANGE;

    int rA = tid >> 2;              // 0..63
    int cA = (tid & 3) * 4;         // ushort col in A tile
    int rB = tid >> 5;              // 0..7 (and +8)
    int cB = (tid & 31) * 4;        // float col in B tile

    float acc[4][2][4];
#pragma unroll
    for (int mi = 0; mi < 4; mi++)
#pragma unroll
        for (int ni = 0; ni < 2; ni++)
#pragma unroll
            for (int r = 0; r < 4; r++) acc[mi][ni][r] = 0.0f;

    // prefetch chunk 0
    uint2 rah, ral; float4 rb0, rb1;
    {
        int k0 = kb;
        rah = *reinterpret_cast<const uint2*>(&g_Ah[rA * NN + k0 + cA]);
        ral = *reinterpret_cast<const uint2*>(&g_Al[rA * NN + k0 + cA]);
        rb0 = *reinterpret_cast<const float4*>(&w3[(size_t)(k0 + rB) * NN + n0 + cB]);
        rb1 = *reinterpret_cast<const float4*>(&w3[(size_t)(k0 + rB + 8) * NN + n0 + cB]);
    }

    uint32_t aAh = (uint32_t)__cvta_generic_to_shared(
        &sAh[0][(lane & 15)][(lane >> 4) * 8]);
    uint32_t aAl = (uint32_t)__cvta_generic_to_shared(
        &sAl[0][(lane & 15)][(lane >> 4) * 8]);
    uint32_t aBh = (uint32_t)__cvta_generic_to_shared(
        &sBh[0][(lane & 15)][warp * 16]);
    uint32_t aBl = (uint32_t)__cvta_generic_to_shared(
        &sBl[0][(lane & 15)][warp * 16]);
    const uint32_t strideAbuf = MB * 16 * 2;
    const uint32_t strideBbuf = 16 * GEMM_BN * 2;

    int p = 0;
#pragma unroll 1
    for (int ck = 0; ck < GEMM_NCHUNK; ck++) {
        {
            *reinterpret_cast<uint2*>(&sAh[p][rA][cA]) = rah;
            *reinterpret_cast<uint2*>(&sAl[p][rA][cA]) = ral;
            uint32_t h0, l0, h1, l1;
            split2_fast(rb0.x, rb0.y, h0, l0);
            split2_fast(rb0.z, rb0.w, h1, l1);
            *reinterpret_cast<uint2*>(&sBh[p][rB][cB]) = make_uint2(h0, h1);
            *reinterpret_cast<uint2*>(&sBl[p][rB][cB]) = make_uint2(l0, l1);
            split2_fast(rb1.x, rb1.y, h0, l0);
            split2_fast(rb1.z, rb1.w, h1, l1);
            *reinterpret_cast<uint2*>(&sBh[p][rB + 8][cB]) = make_uint2(h0, h1);
            *reinterpret_cast<uint2*>(&sBl[p][rB + 8][cB]) = make_uint2(l0, l1);
        }
        if (ck + 1 < GEMM_NCHUNK) {
            int k0 = kb + (ck + 1) * 16;
            rah = *reinterpret_cast<const uint2*>(&g_Ah[rA * NN + k0 + cA]);
            ral = *reinterpret_cast<const uint2*>(&g_Al[rA * NN + k0 + cA]);
            rb0 = *reinterpret_cast<const float4*>(&w3[(size_t)(k0 + rB) * NN + n0 + cB]);
            rb1 = *reinterpret_cast<const float4*>(&w3[(size_t)(k0 + rB + 8) * NN + n0 + cB]);
        }
        __syncthreads();

        uint32_t aH[4][4], aL[4][4];
#pragma unroll
        for (int mi = 0; mi < 4; mi++) {
            ldsm_x4(aH[mi], aAh + p * strideAbuf + mi * 16 * 16 * 2);
            ldsm_x4(aL[mi], aAl + p * strideAbuf + mi * 16 * 16 * 2);
        }
        uint32_t bH[2][2], bL[2][2];
#pragma unroll
        for (int ni = 0; ni < 2; ni++) {
            ldsm_x2t(bH[ni], aBh + p * strideBbuf + ni * 8 * 2);
            ldsm_x2t(bL[ni], aBl + p * strideBbuf + ni * 8 * 2);
        }
#pragma unroll
        for (int mi = 0; mi < 4; mi++)
#pragma unroll
            for (int ni = 0; ni < 2; ni++) {
                mma_bf16(acc[mi][ni], aH[mi], bH[ni]);
                mma_bf16(acc[mi][ni], aH[mi], bL[ni]);
                mma_bf16(acc[mi][ni], aL[mi], bH[ni]);
            }
        p ^= 1;
        __syncthreads();
    }

    float* part = g_part + (size_t)blockIdx.y * N_TOTAL;
#pragma unroll
    for (int mi = 0; mi < 4; mi++) {
        int row = mi * 16 + g;
#pragma unroll
        for (int ni = 0; ni < 2; ni++) {
            int col = n0 + warp * 16 + ni * 8 + 2 * tg;
            *reinterpret_cast<float2*>(&part[(size_t)row * NN + col]) =
                make_float2(acc[mi][ni][0], acc[mi][ni][1]);
            *reinterpret_cast<float2*>(&part[(size_t)(row + 8) * NN + col]) =
                make_float2(acc[mi][ni][2], acc[mi][ni][3]);
        }
    }
}

// ---------------- kernel 6: reduce split-K partials + b3 --------------------
__global__ void k_red(const float* __restrict__ b3,
                      float* __restrict__ out2, int n4) {  // n4 = N_TOTAL/4
    int i = blockIdx.x * blockDim.x + threadIdx.x;
    if (i < n4) {
        float4 a = reinterpret_cast<const float4*>(b3)[i & (NN / 4 - 1)];
#pragma unroll
        for (int j = 0; j < GEMM_KSPLIT; j++) {
            float4 pv = reinterpret_cast<const float4*>(g_part)[(size_t)j * (N_TOTAL / 4) + i];
            a.x += pv.x; a.y += pv.y; a.z += pv.z; a.w += pv.w;
        }
        reinterpret_cast<float4*>(out2)[i] = a;
    }
}

// ---------------- launch ----------------------------------------------------
extern "C" void kernel_launch(void* const* d_in, const int* in_sizes, int n_in,
                              void* d_out, int out_size) {
    const float* feat = (const float*)d_in[0];
    const int*   src  = (const int*)d_in[1];
    const int*   dst  = (const int*)d_in[2];
    const float* ws1  = (const float*)d_in[3];
    const float* wn1  = (const float*)d_in[4];
    const float* b1   = (const float*)d_in[5];
    const float* ws2  = (const float*)d_in[6];
    const float* wn2  = (const float*)d_in[7];
    const float* b2   = (const float*)d_in[8];
    const float* w3   = (const float*)d_in[9];
    const float* b3   = (const float*)d_in[10];
    float* out = (float*)d_out;

    int N = in_sizes[0];   // 262144
    int E = in_sizes[1];   // 2097152

    // side stream: footprint-light L2 prefetch of w3 (overlaps graph chain)
    cudaStream_t s2;
    cudaStreamCreateWithFlags(&s2, cudaStreamNonBlocking);
    cudaEvent_t eF, eJ;
    cudaEventCreateWithFlags(&eF, cudaEventDisableTiming);
    cudaEventCreateWithFlags(&eJ, cudaEventDisableTiming);

    cudaEventRecord(eF, 0);
    cudaStreamWaitEvent(s2, eF, 0);
    k_pref<<<128, 256, 0, s2>>>(w3);
    cudaEventRecord(eJ, s2);

    k_zero<<<(N / 4 + 255) / 256, 256>>>(N / 4);
    k_edge1<<<(E + 255) / 256, 256>>>(feat, src, dst, E);
    k_node1<<<(N + 255) / 256, 256>>>(feat, ws1, wn1, b1, ws2, wn2, N);
    k_edge2<<<(E + 255) / 256, 256>>>(src, dst, E);
    k_node2<<<(N + 255) / 256, 256>>>(b2, out, N);

    cudaStreamWaitEvent(0, eJ, 0);
    dim3 grid(NN / GEMM_BN, GEMM_KSPLIT);
    k_gemm<<<grid, 256>>>(w3);
    k_red<<<(N / 4 + 255) / 256, 256>>>(b3, out + N, N / 4);
}

// round 6
// speedup vs baseline: 1.3038x; 1.1213x over previous
#include <cuda_runtime.h>
#include <cuda_bf16.h>
#include <cstdint>

// Shapes (fixed for this problem)
#define N_TOTAL (64 * 4096)      // 262144 nodes
#define NHID    128
#define NN      4096             // nodes per graph == w3 dim
#define MB      64               // batch (graphs)

// table for s(f,g), t(f,g): range [-6,6]^2, h = 3/32, 129x129 points
#define TAB_N    129
#define TAB_LO   (-6.0f)
#define TAB_INVH (32.0f / 3.0f)

// ---------------- scratch (device globals; no allocation allowed) ----------
__device__ __align__(16) float2 g_fd [N_TOTAL];   // {agg1, deg} interleaved
__device__ float g_s   [N_TOTAL];
__device__ float g_t   [N_TOTAL];
__device__ float g_agg2[N_TOTAL];
#define GEMM_KSPLIT 8
__device__ float g_part[GEMM_KSPLIT * N_TOTAL];        // split-K partials (8MB)
__device__ __align__(16) unsigned short g_Ah[N_TOTAL]; // A bf16 hi
__device__ __align__(16) unsigned short g_Al[N_TOTAL]; // A bf16 lo
__device__ __align__(16) float2 g_tab[TAB_N * TAB_N];  // {s,t} table (133KB)

#define C_2LOG2E 2.88539008177792681f   // 2*log2(e)

__device__ __forceinline__ float ex2f(float x) {
    float e; asm("ex2.approx.f32 %0, %1;" : "=f"(e) : "f"(x)); return e;
}
__device__ __forceinline__ float rcpf(float x) {
    float r; asm("rcp.approx.f32 %0, %1;" : "=f"(r) : "f"(x)); return r;
}
// tanh from prescaled xp = 2*log2e*x : tanh = 1 - 2/(exp2(xp)+1)
__device__ __forceinline__ float tanh_exp2(float xp) {
    return fmaf(-2.0f, rcpf(ex2f(xp) + 1.0f), 1.0f);
}

// fast hi/lo bf16 split of two floats: hi = truncation (PRMT pack),
// lo = exact residual rounded to bf16 (packed cvt). 6 ops / 2 floats.
__device__ __forceinline__ void split2_fast(float a, float b,
                                            uint32_t& hi, uint32_t& lo) {
    uint32_t ua = __float_as_uint(a), ub = __float_as_uint(b);
    hi = __byte_perm(ua, ub, 0x7632);                   // {a_hi16, b_hi16}
    float ah = __uint_as_float(ua & 0xFFFF0000u);
    float bh = __uint_as_float(ub & 0xFFFF0000u);
    float la = a - ah, lb = b - bh;
    asm("cvt.rn.satfinite.bf16x2.f32 %0, %1, %2;" : "=r"(lo) : "f"(lb), "f"(la));
}

// ---------------- side-branch: build s/t table (footprint-light) ------------
__global__ void k_tab(const float* __restrict__ ws1, const float* __restrict__ wn1,
                      const float* __restrict__ b1,
                      const float* __restrict__ ws2, const float* __restrict__ wn2) {
    int p = blockIdx.x * blockDim.x + threadIdx.x;
    if (p >= TAB_N * TAB_N) return;
    int fi = p % TAB_N, gi = p / TAB_N;
    float f = TAB_LO + fi * (1.0f / TAB_INVH);
    float g = TAB_LO + gi * (1.0f / TAB_INVH);
    float s = 0.0f, t = 0.0f;
#pragma unroll 4
    for (int j = 0; j < NHID; j++) {
        float xp = C_2LOG2E * fmaf(f, __ldg(&ws1[j]),
                                   fmaf(g, __ldg(&wn1[j]), __ldg(&b1[j])));
        float r = tanh_exp2(xp);
        s = fmaf(r, __ldg(&ws2[j]), s);
        t = fmaf(r, __ldg(&wn2[j]), t);
    }
    g_tab[p] = make_float2(s, t);
}

// ---------------- kernel 0: zero scratch (vectorized) -----------------------
__global__ void k_zero(int n4) {   // n4 = N_TOTAL/4
    int i = blockIdx.x * blockDim.x + threadIdx.x;
    if (i < n4) {
        float4 z = make_float4(0.f, 0.f, 0.f, 0.f);
        reinterpret_cast<float4*>(g_fd)[2 * i]     = z;
        reinterpret_cast<float4*>(g_fd)[2 * i + 1] = z;
        reinterpret_cast<float4*>(g_agg2)[i]       = z;
    }
}

// ---------------- kernel 1: edge scatter pass 1 ({agg1,deg} v2 red) ---------
__global__ void k_edge1(const float* __restrict__ feat,
                        const int* __restrict__ src,
                        const int* __restrict__ dst, int E) {
    int e = blockIdx.x * blockDim.x + threadIdx.x;
    if (e < E) {
        int s = src[e];
        int d = dst[e];
        float v = __ldg(&feat[s]);
        asm volatile("red.global.add.v2.f32 [%0], {%1, %2};"
                     :: "l"(g_fd + d), "f"(v), "f"(1.0f) : "memory");
    }
}

// ---------------- kernel 2: per-node s,t via bicubic table lookup -----------
// Lagrange cubic weights for frac x, taps at i-1..i+2:
//  w0=-x(x-1)(x-2)/6, w1=(x+1)(x-1)(x-2)/2, w2=-(x+1)x(x-2)/2, w3=(x+1)x(x-1)/6
__device__ __forceinline__ void cubic_w(float x, float w[4]) {
    float xm1 = x - 1.0f, xm2 = x - 2.0f, xp1 = x + 1.0f;
    float a = xm1 * xm2;        // (x-1)(x-2)
    float b = xp1 * x;          // (x+1)x
    w[0] = -x * a * (1.0f / 6.0f);
    w[1] = xp1 * a * 0.5f;
    w[2] = -b * xm2 * 0.5f;
    w[3] = b * xm1 * (1.0f / 6.0f);
}

__global__ __launch_bounds__(256) void k_node1(const float* __restrict__ feat,
                                               int n_total) {
    int n = blockIdx.x * blockDim.x + threadIdx.x;
    if (n >= n_total) return;

    float f   = feat[n];
    float2 fd = g_fd[n];
    float g   = __fdividef(fd.x, fmaxf(fd.y, 1.0f));

    float u = fminf(fmaxf((f - TAB_LO) * TAB_INVH, 1.0f), (float)(TAB_N - 3) - 1e-3f);
    float v = fminf(fmaxf((g - TAB_LO) * TAB_INVH, 1.0f), (float)(TAB_N - 3) - 1e-3f);
    int iu = (int)u;  float x = u - iu;
    int iv = (int)v;  float y = v - iv;

    float wx[4], wy[4];
    cubic_w(x, wx);
    cubic_w(y, wy);

    const float2* base = g_tab + (iv - 1) * TAB_N + (iu - 1);
    float s = 0.0f, t = 0.0f;
#pragma unroll
    for (int a = 0; a < 4; a++) {
        const float2* row = base + a * TAB_N;
        float rs = 0.0f, rt = 0.0f;
#pragma unroll
        for (int b = 0; b < 4; b++) {
            float2 tv = __ldg(&row[b]);
            rs = fmaf(wx[b], tv.x, rs);
            rt = fmaf(wx[b], tv.y, rt);
        }
        s = fmaf(wy[a], rs, s);
        t = fmaf(wy[a], rt, t);
    }
    g_s[n] = s;
    g_t[n] = t;
}

// ---------------- kernel 3: edge scatter pass 2 (agg2 of t) -----------------
__global__ void k_edge2(const int* __restrict__ src,
                        const int* __restrict__ dst, int E) {
    int e = blockIdx.x * blockDim.x + threadIdx.x;
    if (e < E) {
        atomicAdd(&g_agg2[dst[e]], __ldg(&g_t[src[e]]));
    }
}

// ---------------- kernel 4: out1; A = split(tanh(out1)) ---------------------
__global__ void k_node2(const float* __restrict__ b2,
                        float* __restrict__ out, int n_total) {
    int n = blockIdx.x * blockDim.x + threadIdx.x;
    if (n < n_total) {
        float o = g_s[n] + __fdividef(g_agg2[n], fmaxf(g_fd[n].y, 1.0f)) + b2[0];
        out[n] = o;                          // output1
        float h = tanh_exp2(C_2LOG2E * o);
        __nv_bfloat16 hh = __float2bfloat16_rn(h);
        float lo = h - __bfloat162float(hh);
        __nv_bfloat16 hl = __float2bfloat16_rn(lo);
        g_Ah[n] = *reinterpret_cast<unsigned short*>(&hh);
        g_Al[n] = *reinterpret_cast<unsigned short*>(&hl);
    }
}

// ---------------- kernel 5: GEMM partials = h2 @ w3 (bf16 3-pass split) -----
// A preconverted (g_Ah/g_Al); B converted inline with split2_fast.
// Grid: 32 n-tiles (BN=128) x KSPLIT=8; non-atomic partial stores.
#define GEMM_BN 128
#define GEMM_KRANGE (NN / GEMM_KSPLIT)   // 512
#define GEMM_NCHUNK (GEMM_KRANGE / 16)   // 32

__device__ __forceinline__ void mma_bf16(float c[4], const uint32_t a[4],
                                         const uint32_t b[2]) {
    asm volatile(
        "mma.sync.aligned.m16n8k16.row.col.f32.bf16.bf16.f32 "
        "{%0,%1,%2,%3}, {%4,%5,%6,%7}, {%8,%9}, {%0,%1,%2,%3};\n"
        : "+f"(c[0]), "+f"(c[1]), "+f"(c[2]), "+f"(c[3])
        : "r"(a[0]), "r"(a[1]), "r"(a[2]), "r"(a[3]), "r"(b[0]), "r"(b[1]));
}
__device__ __forceinline__ void ldsm_x4(uint32_t r[4], uint32_t addr) {
    asm volatile("ldmatrix.sync.aligned.m8n8.x4.shared.b16 {%0,%1,%2,%3}, [%4];"
                 : "=r"(r[0]), "=r"(r[1]), "=r"(r[2]), "=r"(r[3]) : "r"(addr));
}
__device__ __forceinline__ void ldsm_x2t(uint32_t r[2], uint32_t addr) {
    asm volatile("ldmatrix.sync.aligned.m8n8.x2.trans.shared.b16 {%0,%1}, [%2];"
                 : "=r"(r[0]), "=r"(r[1]) : "r"(addr));
}

__global__ __launch_bounds__(256) void k_gemm(const float* __restrict__ w3) {
    __shared__ __align__(16) unsigned short sAh[2][MB][16], sAl[2][MB][16];
    __shared__ __align__(16) unsigned short sBh[2][16][GEMM_BN], sBl[2][16][GEMM_BN];

    int tid  = threadIdx.x;
    int warp = tid >> 5;
    int lane = tid & 31;
    int g    = lane >> 2;
    int tg   = lane & 3;
    int n0   = blockIdx.x * GEMM_BN;
    int kb   = blockIdx.y * GEMM_KRANGE;

    int rA = tid >> 2;              // 0..63
    int cA = (tid & 3) * 4;         // ushort col in A tile
    int rB = tid >> 5;              // 0..7 (and +8)
    int cB = (tid & 31) * 4;        // float col in B tile

    float acc[4][2][4];
#pragma unroll
    for (int mi = 0; mi < 4; mi++)
#pragma unroll
        for (int ni = 0; ni < 2; ni++)
#pragma unroll
            for (int r = 0; r < 4; r++) acc[mi][ni][r] = 0.0f;

    // prefetch chunk 0
    uint2 rah, ral; float4 rb0, rb1;
    {
        int k0 = kb;
        rah = *reinterpret_cast<const uint2*>(&g_Ah[rA * NN + k0 + cA]);
        ral = *reinterpret_cast<const uint2*>(&g_Al[rA * NN + k0 + cA]);
        rb0 = *reinterpret_cast<const float4*>(&w3[(size_t)(k0 + rB) * NN + n0 + cB]);
        rb1 = *reinterpret_cast<const float4*>(&w3[(size_t)(k0 + rB + 8) * NN + n0 + cB]);
    }

    uint32_t aAh = (uint32_t)__cvta_generic_to_shared(
        &sAh[0][(lane & 15)][(lane >> 4) * 8]);
    uint32_t aAl = (uint32_t)__cvta_generic_to_shared(
        &sAl[0][(lane & 15)][(lane >> 4) * 8]);
    uint32_t aBh = (uint32_t)__cvta_generic_to_shared(
        &sBh[0][(lane & 15)][warp * 16]);
    uint32_t aBl = (uint32_t)__cvta_generic_to_shared(
        &sBl[0][(lane & 15)][warp * 16]);
    const uint32_t strideAbuf = MB * 16 * 2;
    const uint32_t strideBbuf = 16 * GEMM_BN * 2;

    int p = 0;
#pragma unroll 1
    for (int ck = 0; ck < GEMM_NCHUNK; ck++) {
        {
            *reinterpret_cast<uint2*>(&sAh[p][rA][cA]) = rah;
            *reinterpret_cast<uint2*>(&sAl[p][rA][cA]) = ral;
            uint32_t h0, l0, h1, l1;
            split2_fast(rb0.x, rb0.y, h0, l0);
            split2_fast(rb0.z, rb0.w, h1, l1);
            *reinterpret_cast<uint2*>(&sBh[p][rB][cB]) = make_uint2(h0, h1);
            *reinterpret_cast<uint2*>(&sBl[p][rB][cB]) = make_uint2(l0, l1);
            split2_fast(rb1.x, rb1.y, h0, l0);
            split2_fast(rb1.z, rb1.w, h1, l1);
            *reinterpret_cast<uint2*>(&sBh[p][rB + 8][cB]) = make_uint2(h0, h1);
            *reinterpret_cast<uint2*>(&sBl[p][rB + 8][cB]) = make_uint2(l0, l1);
        }
        if (ck + 1 < GEMM_NCHUNK) {
            int k0 = kb + (ck + 1) * 16;
            rah = *reinterpret_cast<const uint2*>(&g_Ah[rA * NN + k0 + cA]);
            ral = *reinterpret_cast<const uint2*>(&g_Al[rA * NN + k0 + cA]);
            rb0 = *reinterpret_cast<const float4*>(&w3[(size_t)(k0 + rB) * NN + n0 + cB]);
            rb1 = *reinterpret_cast<const float4*>(&w3[(size_t)(k0 + rB + 8) * NN + n0 + cB]);
        }
        __syncthreads();

        uint32_t aH[4][4], aL[4][4];
#pragma unroll
        for (int mi = 0; mi < 4; mi++) {
            ldsm_x4(aH[mi], aAh + p * strideAbuf + mi * 16 * 16 * 2);
            ldsm_x4(aL[mi], aAl + p * strideAbuf + mi * 16 * 16 * 2);
        }
        uint32_t bH[2][2], bL[2][2];
#pragma unroll
        for (int ni = 0; ni < 2; ni++) {
            ldsm_x2t(bH[ni], aBh + p * strideBbuf + ni * 8 * 2);
            ldsm_x2t(bL[ni], aBl + p * strideBbuf + ni * 8 * 2);
        }
#pragma unroll
        for (int mi = 0; mi < 4; mi++)
#pragma unroll
            for (int ni = 0; ni < 2; ni++) {
                mma_bf16(acc[mi][ni], aH[mi], bH[ni]);
                mma_bf16(acc[mi][ni], aH[mi], bL[ni]);
                mma_bf16(acc[mi][ni], aL[mi], bH[ni]);
            }
        p ^= 1;
    }

    float* part = g_part + (size_t)blockIdx.y * N_TOTAL;
#pragma unroll
    for (int mi = 0; mi < 4; mi++) {
        int row = mi * 16 + g;
#pragma unroll
        for (int ni = 0; ni < 2; ni++) {
            int col = n0 + warp * 16 + ni * 8 + 2 * tg;
            *reinterpret_cast<float2*>(&part[(size_t)row * NN + col]) =
                make_float2(acc[mi][ni][0], acc[mi][ni][1]);
            *reinterpret_cast<float2*>(&part[(size_t)(row + 8) * NN + col]) =
                make_float2(acc[mi][ni][2], acc[mi][ni][3]);
        }
    }
}

// ---------------- kernel 6: reduce split-K partials + b3 --------------------
__global__ void k_red(const float* __restrict__ b3,
                      float* __restrict__ out2, int n4) {  // n4 = N_TOTAL/4
    int i = blockIdx.x * blockDim.x + threadIdx.x;
    if (i < n4) {
        float4 a = reinterpret_cast<const float4*>(b3)[i & (NN / 4 - 1)];
#pragma unroll
        for (int j = 0; j < GEMM_KSPLIT; j++) {
            float4 pv = reinterpret_cast<const float4*>(g_part)[(size_t)j * (N_TOTAL / 4) + i];
            a.x += pv.x; a.y += pv.y; a.z += pv.z; a.w += pv.w;
        }
        reinterpret_cast<float4*>(out2)[i] = a;
    }
}

// ---------------- launch ----------------------------------------------------
extern "C" void kernel_launch(void* const* d_in, const int* in_sizes, int n_in,
                              void* d_out, int out_size) {
    const float* feat = (const float*)d_in[0];
    const int*   src  = (const int*)d_in[1];
    const int*   dst  = (const int*)d_in[2];
    const float* ws1  = (const float*)d_in[3];
    const float* wn1  = (const float*)d_in[4];
    const float* b1   = (const float*)d_in[5];
    const float* ws2  = (const float*)d_in[6];
    const float* wn2  = (const float*)d_in[7];
    const float* b2   = (const float*)d_in[8];
    const float* w3   = (const float*)d_in[9];
    const float* b3   = (const float*)d_in[10];
    float* out = (float*)d_out;

    int N = in_sizes[0];   // 262144
    int E = in_sizes[1];   // 2097152

    // side stream: build s/t table (tiny footprint) overlapped with zero+edge1
    cudaStream_t s2;
    cudaStreamCreateWithFlags(&s2, cudaStreamNonBlocking);
    cudaEvent_t eF, eJ;
    cudaEventCreateWithFlags(&eF, cudaEventDisableTiming);
    cudaEventCreateWithFlags(&eJ, cudaEventDisableTiming);

    cudaEventRecord(eF, 0);
    cudaStreamWaitEvent(s2, eF, 0);
    k_tab<<<(TAB_N * TAB_N + 255) / 256, 256, 0, s2>>>(ws1, wn1, b1, ws2, wn2);
    cudaEventRecord(eJ, s2);

    k_zero<<<(N / 4 + 255) / 256, 256>>>(N / 4);
    k_edge1<<<(E + 255) / 256, 256>>>(feat, src, dst, E);

    cudaStreamWaitEvent(0, eJ, 0);
    k_node1<<<(N + 255) / 256, 256>>>(feat, N);
    k_edge2<<<(E + 255) / 256, 256>>>(src, dst, E);
    k_node2<<<(N + 255) / 256, 256>>>(b2, out, N);

    dim3 grid(NN / GEMM_BN, GEMM_KSPLIT);
    k_gemm<<<grid, 256>>>(w3);
    k_red<<<(N / 4 + 255) / 256, 256>>>(b3, out + N, N / 4);
}